// round 1
// baseline (speedup 1.0000x reference)
#include <cuda_runtime.h>
#include <math.h>

// ---------------- problem constants ----------------
#define B_   2
#define T_   1024
#define C_   768
#define H_   12
#define D_   64
#define L_   12
#define FF_  3072
#define V_   50257
#define BT_  (B_ * T_)      // 2048
#define C3_  (3 * C_)       // 2304

// ---------------- device scratch (no allocations allowed) ----------------
__device__ float g_x  [BT_ * C_];    // residual stream
__device__ float g_h  [BT_ * C_];    // layernorm output
__device__ float g_qkv[BT_ * C3_];   // qkv projections
__device__ float g_y  [BT_ * C_];    // attention output
__device__ float g_ff [BT_ * FF_];   // mlp hidden
__device__ int   g_idx_is64;

// ---------------- idx dtype detection ----------------
// If idx is int64 (LE), odd 32-bit words of the first 2048 words are all zero.
__global__ void detect_idx_kernel(const int* w) {
    __shared__ int found;
    if (threadIdx.x == 0) found = 0;
    __syncthreads();
    for (int i = threadIdx.x; i < BT_ / 2; i += blockDim.x)
        if (w[2 * i + 1] != 0) found = 1;
    __syncthreads();
    if (threadIdx.x == 0) g_idx_is64 = found ? 0 : 1;
}

// ---------------- embedding ----------------
__global__ void embed_kernel(const int* idxw, const float* tok, const float* pos,
                             float* x) {
    int i = blockIdx.x * blockDim.x + threadIdx.x;
    if (i >= BT_ * C_) return;
    int bt = i / C_;
    int c  = i - bt * C_;
    int t  = bt % T_;
    int token = g_idx_is64 ? idxw[2 * bt] : idxw[bt];
    x[i] = tok[(size_t)token * C_ + c] + pos[t * C_ + c];
}

// ---------------- layernorm (one block per row) ----------------
__global__ __launch_bounds__(256)
void ln_kernel(const float* __restrict__ x, float* __restrict__ out,
               const float* __restrict__ s, const float* __restrict__ b) {
    int row = blockIdx.x;
    int tid = threadIdx.x;
    const float* xr = x + (size_t)row * C_;
    float sum = 0.f, sq = 0.f;
    for (int c = tid; c < C_; c += 256) {
        float v = xr[c];
        sum += v; sq += v * v;
    }
    __shared__ float r1[256], r2[256];
    r1[tid] = sum; r2[tid] = sq;
    __syncthreads();
    for (int off = 128; off > 0; off >>= 1) {
        if (tid < off) { r1[tid] += r1[tid + off]; r2[tid] += r2[tid + off]; }
        __syncthreads();
    }
    float mu  = r1[0] * (1.f / C_);
    float var = r2[0] * (1.f / C_) - mu * mu;
    float inv = rsqrtf(var + 1e-5f);
    for (int c = tid; c < C_; c += 256)
        out[(size_t)row * C_ + c] = (xr[c] - mu) * inv * s[c] + b[c];
}

// ---------------- generic tiled SGEMM with fused epilogue ----------------
// C[m,n] = act(A[m,:] @ W[:,n] + bias[n]) (+ Res[m,n])
// act: 0 = none, 1 = exact GELU. M multiple of 64; K multiple of 16; N arbitrary.
#define BM 64
#define BN 64
#define BK 16

__global__ __launch_bounds__(256)
void sgemm_kernel(const float* __restrict__ A, const float* __restrict__ W,
                  const float* __restrict__ bias, const float* __restrict__ Res,
                  float* __restrict__ Cout, int M, int N, int K, int act) {
    __shared__ float As[BK][BM];
    __shared__ float Ws[BK][BN];

    int bn = blockIdx.x * BN;
    int bm = blockIdx.y * BM;
    int tid = threadIdx.x;
    int tx = tid % 16;        // 16 col groups
    int ty = tid / 16;        // 16 row groups

    float c[4][4];
#pragma unroll
    for (int i = 0; i < 4; i++)
#pragma unroll
        for (int j = 0; j < 4; j++) c[i][j] = 0.f;

    int a_kc = tid % 16;
    int a_r  = tid / 16;
    int w_nc = tid % 64;
    int w_kr = tid / 64;
    int wcol = bn + w_nc;

    for (int k0 = 0; k0 < K; k0 += BK) {
#pragma unroll
        for (int i = 0; i < 4; i++) {
            int row = a_r + i * 16;
            As[a_kc][row] = A[(size_t)(bm + row) * K + k0 + a_kc];
        }
#pragma unroll
        for (int i = 0; i < 4; i++) {
            int kk = w_kr + i * 4;
            Ws[kk][w_nc] = (wcol < N) ? W[(size_t)(k0 + kk) * N + wcol] : 0.f;
        }
        __syncthreads();
#pragma unroll
        for (int kk = 0; kk < BK; kk++) {
            float4 a4 = *reinterpret_cast<const float4*>(&As[kk][ty * 4]);
            float4 b4 = *reinterpret_cast<const float4*>(&Ws[kk][tx * 4]);
            float a[4] = {a4.x, a4.y, a4.z, a4.w};
            float b[4] = {b4.x, b4.y, b4.z, b4.w};
#pragma unroll
            for (int i = 0; i < 4; i++)
#pragma unroll
                for (int j = 0; j < 4; j++) c[i][j] += a[i] * b[j];
        }
        __syncthreads();
    }

#pragma unroll
    for (int i = 0; i < 4; i++) {
        int row = bm + ty * 4 + i;
#pragma unroll
        for (int j = 0; j < 4; j++) {
            int col = bn + tx * 4 + j;
            if (col < N) {
                float v = c[i][j];
                if (bias) v += bias[col];
                if (act == 1)
                    v = 0.5f * v * (1.f + erff(v * 0.70710678118654752f));
                size_t o = (size_t)row * N + col;
                if (Res) v += Res[o];
                Cout[o] = v;
            }
        }
    }
}

// ---------------- attention: one CTA per (b, h, q) ----------------
__global__ __launch_bounds__(128)
void attn_kernel(const float* __restrict__ qkv, float* __restrict__ y) {
    int qpos = blockIdx.x;
    int h    = blockIdx.y;
    int b    = blockIdx.z;
    int tid  = threadIdx.x;

    __shared__ float qv[D_];
    __shared__ float s[T_];
    __shared__ float red[128];

    const float scale = 0.125f;  // 1/sqrt(64)
    const float* base = qkv + (size_t)b * T_ * C3_;

    if (tid < D_) qv[tid] = base[(size_t)qpos * C3_ + h * D_ + tid];
    __syncthreads();

    int nk = qpos + 1;
    float lmax = -1e30f;
    for (int j = tid; j < nk; j += 128) {
        const float* kp = base + (size_t)j * C3_ + C_ + h * D_;
        float dot = 0.f;
#pragma unroll
        for (int d = 0; d < D_; d++) dot += qv[d] * kp[d];
        dot *= scale;
        s[j] = dot;
        lmax = fmaxf(lmax, dot);
    }
    red[tid] = lmax;
    __syncthreads();
    for (int off = 64; off > 0; off >>= 1) {
        if (tid < off) red[tid] = fmaxf(red[tid], red[tid + off]);
        __syncthreads();
    }
    float m = red[0];
    __syncthreads();

    float lsum = 0.f;
    for (int j = tid; j < nk; j += 128) {
        float p = expf(s[j] - m);
        s[j] = p;
        lsum += p;
    }
    red[tid] = lsum;
    __syncthreads();
    for (int off = 64; off > 0; off >>= 1) {
        if (tid < off) red[tid] += red[tid + off];
        __syncthreads();
    }
    float inv = 1.f / red[0];
    __syncthreads();

    if (tid < D_) {
        int d = tid;
        const float* vp = base + 2 * C_ + h * D_ + d;
        float acc0 = 0.f, acc1 = 0.f, acc2 = 0.f, acc3 = 0.f;
        int j = 0;
        for (; j + 3 < nk; j += 4) {
            acc0 += s[j]     * vp[(size_t)(j)     * C3_];
            acc1 += s[j + 1] * vp[(size_t)(j + 1) * C3_];
            acc2 += s[j + 2] * vp[(size_t)(j + 2) * C3_];
            acc3 += s[j + 3] * vp[(size_t)(j + 3) * C3_];
        }
        for (; j < nk; j++) acc0 += s[j] * vp[(size_t)j * C3_];
        y[((size_t)(b * T_ + qpos)) * C_ + h * D_ + d] =
            (acc0 + acc1 + acc2 + acc3) * inv;
    }
}

// ---------------- host launcher ----------------
extern "C" void kernel_launch(void* const* d_in, const int* in_sizes, int n_in,
                              void* d_out, int out_size) {
    const int*   idxw    = (const int*)  d_in[0];
    const float* tok_emb = (const float*)d_in[1];
    const float* pos_emb = (const float*)d_in[2];
    const float* ln1_s   = (const float*)d_in[3];
    const float* ln1_b   = (const float*)d_in[4];
    const float* Wqkv    = (const float*)d_in[5];
    const float* bqkv    = (const float*)d_in[6];
    const float* Wo      = (const float*)d_in[7];
    const float* bo      = (const float*)d_in[8];
    const float* ln2_s   = (const float*)d_in[9];
    const float* ln2_b   = (const float*)d_in[10];
    const float* Wfc     = (const float*)d_in[11];
    const float* bfc     = (const float*)d_in[12];
    const float* Wpr     = (const float*)d_in[13];
    const float* bpr     = (const float*)d_in[14];
    const float* lnf_s   = (const float*)d_in[15];
    const float* lnf_b   = (const float*)d_in[16];
    const float* Whead   = (const float*)d_in[17];
    float* out = (float*)d_out;

    float *x, *h, *qkv, *y, *ff;
    cudaGetSymbolAddress((void**)&x,   g_x);
    cudaGetSymbolAddress((void**)&h,   g_h);
    cudaGetSymbolAddress((void**)&qkv, g_qkv);
    cudaGetSymbolAddress((void**)&y,   g_y);
    cudaGetSymbolAddress((void**)&ff,  g_ff);

    detect_idx_kernel<<<1, 256>>>(idxw);
    embed_kernel<<<(BT_ * C_ + 255) / 256, 256>>>(idxw, tok_emb, pos_emb, x);

    dim3 gQKV((C3_ + BN - 1) / BN, BT_ / BM);
    dim3 gPROJ((C_ + BN - 1) / BN, BT_ / BM);
    dim3 gFC((FF_ + BN - 1) / BN, BT_ / BM);
    dim3 gHEAD((V_ + BN - 1) / BN, BT_ / BM);
    dim3 gATT(T_, H_, B_);

    for (int l = 0; l < L_; l++) {
        ln_kernel<<<BT_, 256>>>(x, h, ln1_s + (size_t)l * C_, ln1_b + (size_t)l * C_);
        sgemm_kernel<<<gQKV, 256>>>(h, Wqkv + (size_t)l * C_ * C3_,
                                    bqkv + (size_t)l * C3_, nullptr, qkv,
                                    BT_, C3_, C_, 0);
        attn_kernel<<<gATT, 128>>>(qkv, y);
        sgemm_kernel<<<gPROJ, 256>>>(y, Wo + (size_t)l * C_ * C_,
                                     bo + (size_t)l * C_, x, x,
                                     BT_, C_, C_, 0);
        ln_kernel<<<BT_, 256>>>(x, h, ln2_s + (size_t)l * C_, ln2_b + (size_t)l * C_);
        sgemm_kernel<<<gFC, 256>>>(h, Wfc + (size_t)l * C_ * FF_,
                                   bfc + (size_t)l * FF_, nullptr, ff,
                                   BT_, FF_, C_, 1);
        sgemm_kernel<<<gPROJ, 256>>>(ff, Wpr + (size_t)l * FF_ * C_,
                                     bpr + (size_t)l * C_, x, x,
                                     BT_, C_, FF_, 0);
    }

    ln_kernel<<<BT_, 256>>>(x, h, lnf_s, lnf_b);
    sgemm_kernel<<<gHEAD, 256>>>(h, Whead, nullptr, nullptr, out,
                                 BT_, V_, C_, 0);
}

// round 2
// speedup vs baseline: 1.2640x; 1.2640x over previous
#include <cuda_runtime.h>
#include <math.h>
#include <stdint.h>

// ---------------- problem constants ----------------
#define B_   2
#define T_   1024
#define C_   768
#define H_   12
#define D_   64
#define L_   12
#define FF_  3072
#define V_   50257
#define BT_  (B_ * T_)      // 2048
#define C3_  (3 * C_)       // 2304

// ---------------- device scratch ----------------
__device__ float g_x  [BT_ * C_];
__device__ float g_h  [BT_ * C_];
__device__ float g_qkv[BT_ * C3_];
__device__ float g_y  [BT_ * C_];
__device__ float g_ff [BT_ * FF_];
__device__ int   g_idx_is64;

// ---------------- idx dtype detection ----------------
__global__ void detect_idx_kernel(const int* w) {
    __shared__ int found;
    if (threadIdx.x == 0) found = 0;
    __syncthreads();
    for (int i = threadIdx.x; i < BT_ / 2; i += blockDim.x)
        if (w[2 * i + 1] != 0) found = 1;
    __syncthreads();
    if (threadIdx.x == 0) g_idx_is64 = found ? 0 : 1;
}

// ---------------- embedding ----------------
__global__ void embed_kernel(const int* idxw, const float* tok, const float* pos,
                             float* x) {
    int i = blockIdx.x * blockDim.x + threadIdx.x;
    if (i >= BT_ * C_) return;
    int bt = i / C_;
    int c  = i - bt * C_;
    int t  = bt % T_;
    int token = g_idx_is64 ? idxw[2 * bt] : idxw[bt];
    x[i] = tok[(size_t)token * C_ + c] + pos[t * C_ + c];
}

// ---------------- layernorm ----------------
__global__ __launch_bounds__(256)
void ln_kernel(const float* __restrict__ x, float* __restrict__ out,
               const float* __restrict__ s, const float* __restrict__ b) {
    int row = blockIdx.x;
    int tid = threadIdx.x;
    const float* xr = x + (size_t)row * C_;
    float sum = 0.f, sq = 0.f;
    for (int c = tid; c < C_; c += 256) {
        float v = xr[c];
        sum += v; sq += v * v;
    }
    __shared__ float r1[256], r2[256];
    r1[tid] = sum; r2[tid] = sq;
    __syncthreads();
    for (int off = 128; off > 0; off >>= 1) {
        if (tid < off) { r1[tid] += r1[tid + off]; r2[tid] += r2[tid + off]; }
        __syncthreads();
    }
    float mu  = r1[0] * (1.f / C_);
    float var = r2[0] * (1.f / C_) - mu * mu;
    float inv = rsqrtf(var + 1e-5f);
    for (int c = tid; c < C_; c += 256)
        out[(size_t)row * C_ + c] = (xr[c] - mu) * inv * s[c] + b[c];
}

// ---------------- tf32 tensor-core GEMM ----------------
// C[m,n] = act(A[m,:] @ W[:,n] + bias[n]) (+ Res[m,n])
// CTA tile 128x64, BK=16. 8 warps: 4(m) x 2(n), warp tile 32x32.
// mma.sync.m16n8k8 tf32, fp32 accumulate. M multiple of 128, K multiple of 16.

#define TBM 128
#define TBN 64
#define TBK 16
#define AS_LD 136   // 136 mod 32 == 8 -> conflict-free frag loads
#define WS_LD 72    //  72 mod 32 == 8

__device__ __forceinline__ float to_tf32(float x) {
    uint32_t u;
    asm("cvt.rna.tf32.f32 %0, %1;" : "=r"(u) : "f"(x));
    return __uint_as_float(u);
}

__device__ __forceinline__ void mma_tf32(float* c, const uint32_t* a, const uint32_t* b) {
    asm volatile(
        "mma.sync.aligned.m16n8k8.row.col.f32.tf32.tf32.f32 "
        "{%0,%1,%2,%3}, {%4,%5,%6,%7}, {%8,%9}, {%0,%1,%2,%3};"
        : "+f"(c[0]), "+f"(c[1]), "+f"(c[2]), "+f"(c[3])
        : "r"(a[0]), "r"(a[1]), "r"(a[2]), "r"(a[3]), "r"(b[0]), "r"(b[1]));
}

__global__ __launch_bounds__(256)
void tgemm_kernel(const float* __restrict__ A, const float* __restrict__ W,
                  const float* __restrict__ bias, const float* __restrict__ Res,
                  float* __restrict__ Cout, int M, int N, int K, int act) {
    __shared__ float As[TBK][AS_LD];   // [k][m]
    __shared__ float Ws[TBK][WS_LD];   // [k][n]

    int bn = blockIdx.x * TBN;
    int bm = blockIdx.y * TBM;
    int tid  = threadIdx.x;
    int lane = tid & 31;
    int warp = tid >> 5;
    int wm = warp >> 1;        // 0..3
    int wn = warp & 1;         // 0..1
    int g   = lane >> 2;       // 0..7
    int tig = lane & 3;        // 0..3

    float acc[2][4][4];
#pragma unroll
    for (int mi = 0; mi < 2; mi++)
#pragma unroll
        for (int ni = 0; ni < 4; ni++)
#pragma unroll
            for (int e = 0; e < 4; e++) acc[mi][ni][e] = 0.f;

    // A load mapping: 2 iterations, thread covers row m = tid/4 + 64*it, float4 f = tid%4
    int a_m = tid >> 2;
    int a_f = (tid & 3) * 4;
    // W load mapping: row k = tid/16, float4 col group = tid%16
    int w_k = tid >> 4;
    int w_f = (tid & 15) * 4;
    bool nvec = ((N & 3) == 0);

    for (int k0 = 0; k0 < K; k0 += TBK) {
        // --- load A tile (128 x 16) ---
#pragma unroll
        for (int it = 0; it < 2; it++) {
            int m = a_m + it * 64;
            float4 v = *reinterpret_cast<const float4*>(
                &A[(size_t)(bm + m) * K + k0 + a_f]);
            As[a_f + 0][m] = to_tf32(v.x);
            As[a_f + 1][m] = to_tf32(v.y);
            As[a_f + 2][m] = to_tf32(v.z);
            As[a_f + 3][m] = to_tf32(v.w);
        }
        // --- load W tile (16 x 64) ---
        {
            int col = bn + w_f;
            if (nvec && col + 3 < N) {
                float4 v = *reinterpret_cast<const float4*>(
                    &W[(size_t)(k0 + w_k) * N + col]);
                float4 o;
                o.x = to_tf32(v.x); o.y = to_tf32(v.y);
                o.z = to_tf32(v.z); o.w = to_tf32(v.w);
                *reinterpret_cast<float4*>(&Ws[w_k][w_f]) = o;
            } else {
#pragma unroll
                for (int j = 0; j < 4; j++)
                    Ws[w_k][w_f + j] = (col + j < N)
                        ? to_tf32(W[(size_t)(k0 + w_k) * N + col + j]) : 0.f;
            }
        }
        __syncthreads();

        // --- compute: 2 k8-steps ---
#pragma unroll
        for (int ks = 0; ks < 2; ks++) {
            int kb = ks * 8;
            uint32_t af[2][4], bf[4][2];
#pragma unroll
            for (int mi = 0; mi < 2; mi++) {
                int m0 = wm * 32 + mi * 16;
                af[mi][0] = __float_as_uint(As[kb + tig    ][m0 + g    ]);
                af[mi][1] = __float_as_uint(As[kb + tig    ][m0 + g + 8]);
                af[mi][2] = __float_as_uint(As[kb + tig + 4][m0 + g    ]);
                af[mi][3] = __float_as_uint(As[kb + tig + 4][m0 + g + 8]);
            }
#pragma unroll
            for (int ni = 0; ni < 4; ni++) {
                int n0 = wn * 32 + ni * 8;
                bf[ni][0] = __float_as_uint(Ws[kb + tig    ][n0 + g]);
                bf[ni][1] = __float_as_uint(Ws[kb + tig + 4][n0 + g]);
            }
#pragma unroll
            for (int mi = 0; mi < 2; mi++)
#pragma unroll
                for (int ni = 0; ni < 4; ni++)
                    mma_tf32(acc[mi][ni], af[mi], bf[ni]);
        }
        __syncthreads();
    }

    // --- epilogue ---
#pragma unroll
    for (int mi = 0; mi < 2; mi++) {
        int r0 = bm + wm * 32 + mi * 16 + g;
#pragma unroll
        for (int ni = 0; ni < 4; ni++) {
            int col0 = bn + wn * 32 + ni * 8 + 2 * tig;
#pragma unroll
            for (int e = 0; e < 4; e++) {
                int row = r0 + (e >> 1) * 8;
                int col = col0 + (e & 1);
                if (col < N) {
                    float v = acc[mi][ni][e];
                    if (bias) v += bias[col];
                    if (act == 1)
                        v = 0.5f * v * (1.f + erff(v * 0.70710678118654752f));
                    size_t o = (size_t)row * N + col;
                    if (Res) v += Res[o];
                    Cout[o] = v;
                }
            }
        }
    }
}

// ---------------- attention: one CTA per (b, h, q) ----------------
__global__ __launch_bounds__(128)
void attn_kernel(const float* __restrict__ qkv, float* __restrict__ y) {
    int qpos = blockIdx.x;
    int h    = blockIdx.y;
    int b    = blockIdx.z;
    int tid  = threadIdx.x;

    __shared__ float qv[D_];
    __shared__ float s[T_];
    __shared__ float red[128];

    const float scale = 0.125f;
    const float* base = qkv + (size_t)b * T_ * C3_;

    if (tid < D_) qv[tid] = base[(size_t)qpos * C3_ + h * D_ + tid];
    __syncthreads();

    int nk = qpos + 1;
    float lmax = -1e30f;
    for (int j = tid; j < nk; j += 128) {
        const float* kp = base + (size_t)j * C3_ + C_ + h * D_;
        float dot = 0.f;
#pragma unroll
        for (int d = 0; d < D_; d++) dot += qv[d] * kp[d];
        dot *= scale;
        s[j] = dot;
        lmax = fmaxf(lmax, dot);
    }
    red[tid] = lmax;
    __syncthreads();
    for (int off = 64; off > 0; off >>= 1) {
        if (tid < off) red[tid] = fmaxf(red[tid], red[tid + off]);
        __syncthreads();
    }
    float m = red[0];
    __syncthreads();

    float lsum = 0.f;
    for (int j = tid; j < nk; j += 128) {
        float p = expf(s[j] - m);
        s[j] = p;
        lsum += p;
    }
    red[tid] = lsum;
    __syncthreads();
    for (int off = 64; off > 0; off >>= 1) {
        if (tid < off) red[tid] += red[tid + off];
        __syncthreads();
    }
    float inv = 1.f / red[0];
    __syncthreads();

    if (tid < D_) {
        int d = tid;
        const float* vp = base + 2 * C_ + h * D_ + d;
        float acc0 = 0.f, acc1 = 0.f, acc2 = 0.f, acc3 = 0.f;
        int j = 0;
        for (; j + 3 < nk; j += 4) {
            acc0 += s[j]     * vp[(size_t)(j)     * C3_];
            acc1 += s[j + 1] * vp[(size_t)(j + 1) * C3_];
            acc2 += s[j + 2] * vp[(size_t)(j + 2) * C3_];
            acc3 += s[j + 3] * vp[(size_t)(j + 3) * C3_];
        }
        for (; j < nk; j++) acc0 += s[j] * vp[(size_t)j * C3_];
        y[((size_t)(b * T_ + qpos)) * C_ + h * D_ + d] =
            (acc0 + acc1 + acc2 + acc3) * inv;
    }
}

// ---------------- host launcher ----------------
extern "C" void kernel_launch(void* const* d_in, const int* in_sizes, int n_in,
                              void* d_out, int out_size) {
    const int*   idxw    = (const int*)  d_in[0];
    const float* tok_emb = (const float*)d_in[1];
    const float* pos_emb = (const float*)d_in[2];
    const float* ln1_s   = (const float*)d_in[3];
    const float* ln1_b   = (const float*)d_in[4];
    const float* Wqkv    = (const float*)d_in[5];
    const float* bqkv    = (const float*)d_in[6];
    const float* Wo      = (const float*)d_in[7];
    const float* bo      = (const float*)d_in[8];
    const float* ln2_s   = (const float*)d_in[9];
    const float* ln2_b   = (const float*)d_in[10];
    const float* Wfc     = (const float*)d_in[11];
    const float* bfc     = (const float*)d_in[12];
    const float* Wpr     = (const float*)d_in[13];
    const float* bpr     = (const float*)d_in[14];
    const float* lnf_s   = (const float*)d_in[15];
    const float* lnf_b   = (const float*)d_in[16];
    const float* Whead   = (const float*)d_in[17];
    float* out = (float*)d_out;

    float *x, *h, *qkv, *y, *ff;
    cudaGetSymbolAddress((void**)&x,   g_x);
    cudaGetSymbolAddress((void**)&h,   g_h);
    cudaGetSymbolAddress((void**)&qkv, g_qkv);
    cudaGetSymbolAddress((void**)&y,   g_y);
    cudaGetSymbolAddress((void**)&ff,  g_ff);

    detect_idx_kernel<<<1, 256>>>(idxw);
    embed_kernel<<<(BT_ * C_ + 255) / 256, 256>>>(idxw, tok_emb, pos_emb, x);

    dim3 gQKV((C3_ + TBN - 1) / TBN, BT_ / TBM);
    dim3 gPROJ((C_ + TBN - 1) / TBN, BT_ / TBM);
    dim3 gFC((FF_ + TBN - 1) / TBN, BT_ / TBM);
    dim3 gHEAD((V_ + TBN - 1) / TBN, BT_ / TBM);
    dim3 gATT(T_, H_, B_);

    for (int l = 0; l < L_; l++) {
        ln_kernel<<<BT_, 256>>>(x, h, ln1_s + (size_t)l * C_, ln1_b + (size_t)l * C_);
        tgemm_kernel<<<gQKV, 256>>>(h, Wqkv + (size_t)l * C_ * C3_,
                                    bqkv + (size_t)l * C3_, nullptr, qkv,
                                    BT_, C3_, C_, 0);
        attn_kernel<<<gATT, 128>>>(qkv, y);
        tgemm_kernel<<<gPROJ, 256>>>(y, Wo + (size_t)l * C_ * C_,
                                     bo + (size_t)l * C_, x, x,
                                     BT_, C_, C_, 0);
        ln_kernel<<<BT_, 256>>>(x, h, ln2_s + (size_t)l * C_, ln2_b + (size_t)l * C_);
        tgemm_kernel<<<gFC, 256>>>(h, Wfc + (size_t)l * C_ * FF_,
                                   bfc + (size_t)l * FF_, nullptr, ff,
                                   BT_, FF_, C_, 1);
        tgemm_kernel<<<gPROJ, 256>>>(ff, Wpr + (size_t)l * FF_ * C_,
                                     bpr + (size_t)l * C_, x, x,
                                     BT_, C_, FF_, 0);
    }

    ln_kernel<<<BT_, 256>>>(x, h, lnf_s, lnf_b);
    tgemm_kernel<<<gHEAD, 256>>>(h, Whead, nullptr, nullptr, out,
                                 BT_, V_, C_, 0);
}

// round 3
// speedup vs baseline: 4.7634x; 3.7684x over previous
#include <cuda_runtime.h>
#include <math.h>
#include <stdint.h>

// ---------------- problem constants ----------------
#define B_   2
#define T_   1024
#define C_   768
#define H_   12
#define D_   64
#define L_   12
#define FF_  3072
#define V_   50257
#define BT_  (B_ * T_)      // 2048
#define C3_  (3 * C_)       // 2304

// ---------------- device scratch ----------------
__device__ float g_x  [BT_ * C_];
__device__ float g_h  [BT_ * C_];
__device__ float g_qkv[BT_ * C3_];
__device__ float g_y  [BT_ * C_];
__device__ float g_ff [BT_ * FF_];
__device__ int   g_idx_is64;

// ---------------- idx dtype detection ----------------
__global__ void detect_idx_kernel(const int* w) {
    __shared__ int found;
    if (threadIdx.x == 0) found = 0;
    __syncthreads();
    for (int i = threadIdx.x; i < BT_ / 2; i += blockDim.x)
        if (w[2 * i + 1] != 0) found = 1;
    __syncthreads();
    if (threadIdx.x == 0) g_idx_is64 = found ? 0 : 1;
}

// ---------------- embedding ----------------
__global__ void embed_kernel(const int* idxw, const float* tok, const float* pos,
                             float* x) {
    int i = blockIdx.x * blockDim.x + threadIdx.x;
    if (i >= BT_ * C_) return;
    int bt = i / C_;
    int c  = i - bt * C_;
    int t  = bt % T_;
    int token = g_idx_is64 ? idxw[2 * bt] : idxw[bt];
    x[i] = tok[(size_t)token * C_ + c] + pos[t * C_ + c];
}

// ---------------- layernorm ----------------
__global__ __launch_bounds__(256)
void ln_kernel(const float* __restrict__ x, float* __restrict__ out,
               const float* __restrict__ s, const float* __restrict__ b) {
    int row = blockIdx.x;
    int tid = threadIdx.x;
    const float* xr = x + (size_t)row * C_;
    float sum = 0.f, sq = 0.f;
    for (int c = tid; c < C_; c += 256) {
        float v = xr[c];
        sum += v; sq += v * v;
    }
    __shared__ float r1[256], r2[256];
    r1[tid] = sum; r2[tid] = sq;
    __syncthreads();
    for (int off = 128; off > 0; off >>= 1) {
        if (tid < off) { r1[tid] += r1[tid + off]; r2[tid] += r2[tid + off]; }
        __syncthreads();
    }
    float mu  = r1[0] * (1.f / C_);
    float var = r2[0] * (1.f / C_) - mu * mu;
    float inv = rsqrtf(var + 1e-5f);
    for (int c = tid; c < C_; c += 256)
        out[(size_t)row * C_ + c] = (xr[c] - mu) * inv * s[c] + b[c];
}

// ---------------- tf32 tensor-core GEMM ----------------
#define TBM 128
#define TBN 64
#define TBK 16
#define AS_LD 136
#define WS_LD 72

__device__ __forceinline__ float to_tf32(float x) {
    uint32_t u;
    asm("cvt.rna.tf32.f32 %0, %1;" : "=r"(u) : "f"(x));
    return __uint_as_float(u);
}

__device__ __forceinline__ void mma_tf32(float* c, const uint32_t* a, const uint32_t* b) {
    asm volatile(
        "mma.sync.aligned.m16n8k8.row.col.f32.tf32.tf32.f32 "
        "{%0,%1,%2,%3}, {%4,%5,%6,%7}, {%8,%9}, {%0,%1,%2,%3};"
        : "+f"(c[0]), "+f"(c[1]), "+f"(c[2]), "+f"(c[3])
        : "r"(a[0]), "r"(a[1]), "r"(a[2]), "r"(a[3]), "r"(b[0]), "r"(b[1]));
}

__global__ __launch_bounds__(256)
void tgemm_kernel(const float* __restrict__ A, const float* __restrict__ W,
                  const float* __restrict__ bias, const float* __restrict__ Res,
                  float* __restrict__ Cout, int M, int N, int K, int act) {
    __shared__ float As[TBK][AS_LD];
    __shared__ float Ws[TBK][WS_LD];

    int bn = blockIdx.x * TBN;
    int bm = blockIdx.y * TBM;
    int tid  = threadIdx.x;
    int lane = tid & 31;
    int warp = tid >> 5;
    int wm = warp >> 1;
    int wn = warp & 1;
    int g   = lane >> 2;
    int tig = lane & 3;

    float acc[2][4][4];
#pragma unroll
    for (int mi = 0; mi < 2; mi++)
#pragma unroll
        for (int ni = 0; ni < 4; ni++)
#pragma unroll
            for (int e = 0; e < 4; e++) acc[mi][ni][e] = 0.f;

    int a_m = tid >> 2;
    int a_f = (tid & 3) * 4;
    int w_k = tid >> 4;
    int w_f = (tid & 15) * 4;
    bool nvec = ((N & 3) == 0);

    for (int k0 = 0; k0 < K; k0 += TBK) {
#pragma unroll
        for (int it = 0; it < 2; it++) {
            int m = a_m + it * 64;
            float4 v = *reinterpret_cast<const float4*>(
                &A[(size_t)(bm + m) * K + k0 + a_f]);
            As[a_f + 0][m] = to_tf32(v.x);
            As[a_f + 1][m] = to_tf32(v.y);
            As[a_f + 2][m] = to_tf32(v.z);
            As[a_f + 3][m] = to_tf32(v.w);
        }
        {
            int col = bn + w_f;
            if (nvec && col + 3 < N) {
                float4 v = *reinterpret_cast<const float4*>(
                    &W[(size_t)(k0 + w_k) * N + col]);
                float4 o;
                o.x = to_tf32(v.x); o.y = to_tf32(v.y);
                o.z = to_tf32(v.z); o.w = to_tf32(v.w);
                *reinterpret_cast<float4*>(&Ws[w_k][w_f]) = o;
            } else {
#pragma unroll
                for (int j = 0; j < 4; j++)
                    Ws[w_k][w_f + j] = (col + j < N)
                        ? to_tf32(W[(size_t)(k0 + w_k) * N + col + j]) : 0.f;
            }
        }
        __syncthreads();

#pragma unroll
        for (int ks = 0; ks < 2; ks++) {
            int kb = ks * 8;
            uint32_t af[2][4], bf[4][2];
#pragma unroll
            for (int mi = 0; mi < 2; mi++) {
                int m0 = wm * 32 + mi * 16;
                af[mi][0] = __float_as_uint(As[kb + tig    ][m0 + g    ]);
                af[mi][1] = __float_as_uint(As[kb + tig    ][m0 + g + 8]);
                af[mi][2] = __float_as_uint(As[kb + tig + 4][m0 + g    ]);
                af[mi][3] = __float_as_uint(As[kb + tig + 4][m0 + g + 8]);
            }
#pragma unroll
            for (int ni = 0; ni < 4; ni++) {
                int n0 = wn * 32 + ni * 8;
                bf[ni][0] = __float_as_uint(Ws[kb + tig    ][n0 + g]);
                bf[ni][1] = __float_as_uint(Ws[kb + tig + 4][n0 + g]);
            }
#pragma unroll
            for (int mi = 0; mi < 2; mi++)
#pragma unroll
                for (int ni = 0; ni < 4; ni++)
                    mma_tf32(acc[mi][ni], af[mi], bf[ni]);
        }
        __syncthreads();
    }

#pragma unroll
    for (int mi = 0; mi < 2; mi++) {
        int r0 = bm + wm * 32 + mi * 16 + g;
#pragma unroll
        for (int ni = 0; ni < 4; ni++) {
            int col0 = bn + wn * 32 + ni * 8 + 2 * tig;
#pragma unroll
            for (int e = 0; e < 4; e++) {
                int row = r0 + (e >> 1) * 8;
                int col = col0 + (e & 1);
                if (col < N) {
                    float v = acc[mi][ni][e];
                    if (bias) v += bias[col];
                    if (act == 1)
                        v = 0.5f * v * (1.f + erff(v * 0.70710678118654752f));
                    size_t o = (size_t)row * N + col;
                    if (Res) v += Res[o];
                    Cout[o] = v;
                }
            }
        }
    }
}

// ---------------- flash attention: one CTA per (b, h, 64-q tile) ----------------
// smem: Qs[d][r] 64x64, Ks[d][c] 64x64, Vs[k][d] 64x64, Ps[r][k] 64x65, m/l rows.
// 256 threads: thread (ty=tid/16, tx=tid%16) owns rows 4ty..+3, cols 4tx..+3.
#define ATT_SMEM ((3 * 64 * 64 + 64 * 65 + 128) * 4)

__global__ __launch_bounds__(256)
void attn_flash_kernel(const float* __restrict__ qkv, float* __restrict__ y) {
    extern __shared__ float sm[];
    float* Qs   = sm;                    // [64][64] d-major
    float* Ks   = Qs + 64 * 64;          // [64][64] d-major
    float* Vs   = Ks + 64 * 64;          // [64][64] k-major
    float* Ps   = Vs + 64 * 64;          // [64][65]
    float* mrow = Ps + 64 * 65;
    float* lrow = mrow + 64;

    int qt  = blockIdx.x;
    int h   = blockIdx.y;
    int b   = blockIdx.z;
    int tid = threadIdx.x;
    int tx  = tid & 15;
    int ty  = tid >> 4;
    const float scale = 0.125f;
    const float* base = qkv + (size_t)b * T_ * C3_;

    // load Q tile, transpose to d-major
    {
        int r  = tid >> 2;
        int d0 = (tid & 3) * 16;
        const float* qp = base + (size_t)(qt * 64 + r) * C3_ + h * 64 + d0;
#pragma unroll
        for (int i = 0; i < 4; i++) {
            float4 v = *reinterpret_cast<const float4*>(&qp[4 * i]);
            Qs[(d0 + 4 * i + 0) * 64 + r] = v.x;
            Qs[(d0 + 4 * i + 1) * 64 + r] = v.y;
            Qs[(d0 + 4 * i + 2) * 64 + r] = v.z;
            Qs[(d0 + 4 * i + 3) * 64 + r] = v.w;
        }
    }
    if (tid < 64) { mrow[tid] = -1e30f; lrow[tid] = 0.f; }

    float o[4][4];
#pragma unroll
    for (int i = 0; i < 4; i++)
#pragma unroll
        for (int j = 0; j < 4; j++) o[i][j] = 0.f;
    __syncthreads();

    for (int kt = 0; kt <= qt; kt++) {
        // load K (transposed) and V (row-major)
        {
            int r  = tid >> 2;
            int d0 = (tid & 3) * 16;
            const float* kp = base + (size_t)(kt * 64 + r) * C3_ + C_ + h * 64 + d0;
            const float* vp = kp + C_;
#pragma unroll
            for (int i = 0; i < 4; i++) {
                float4 v = *reinterpret_cast<const float4*>(&kp[4 * i]);
                Ks[(d0 + 4 * i + 0) * 64 + r] = v.x;
                Ks[(d0 + 4 * i + 1) * 64 + r] = v.y;
                Ks[(d0 + 4 * i + 2) * 64 + r] = v.z;
                Ks[(d0 + 4 * i + 3) * 64 + r] = v.w;
            }
#pragma unroll
            for (int i = 0; i < 4; i++) {
                float4 v = *reinterpret_cast<const float4*>(&vp[4 * i]);
                *reinterpret_cast<float4*>(&Vs[r * 64 + d0 + 4 * i]) = v;
            }
        }
        __syncthreads();

        // S = Q K^T (16 outputs per thread)
        float cS[4][4];
#pragma unroll
        for (int i = 0; i < 4; i++)
#pragma unroll
            for (int j = 0; j < 4; j++) cS[i][j] = 0.f;
        for (int d = 0; d < 64; d++) {
            float4 aq = *reinterpret_cast<const float4*>(&Qs[d * 64 + 4 * ty]);
            float4 bk = *reinterpret_cast<const float4*>(&Ks[d * 64 + 4 * tx]);
            float a[4] = {aq.x, aq.y, aq.z, aq.w};
            float bb[4] = {bk.x, bk.y, bk.z, bk.w};
#pragma unroll
            for (int i = 0; i < 4; i++)
#pragma unroll
                for (int j = 0; j < 4; j++) cS[i][j] += a[i] * bb[j];
        }

        // online softmax (rows owned by 16-lane group: reduce across tx)
        float al[4];
        bool diag = (kt == qt);
#pragma unroll
        for (int i = 0; i < 4; i++) {
            int r  = 4 * ty + i;
            int qg = qt * 64 + r;
            float rmax = -1e30f;
#pragma unroll
            for (int j = 0; j < 4; j++) {
                float s = cS[i][j] * scale;
                if (diag && (kt * 64 + 4 * tx + j) > qg) s = -1e30f;
                cS[i][j] = s;
                rmax = fmaxf(rmax, s);
            }
#pragma unroll
            for (int off = 8; off > 0; off >>= 1)
                rmax = fmaxf(rmax, __shfl_xor_sync(0xffffffffu, rmax, off));
            float mo = mrow[r];
            float mn = fmaxf(mo, rmax);
            float sum = 0.f;
#pragma unroll
            for (int j = 0; j < 4; j++) {
                float p = __expf(cS[i][j] - mn);
                cS[i][j] = p;
                sum += p;
            }
#pragma unroll
            for (int off = 8; off > 0; off >>= 1)
                sum += __shfl_xor_sync(0xffffffffu, sum, off);
            al[i] = __expf(mo - mn);
            if (tx == 0) {
                mrow[r] = mn;
                lrow[r] = lrow[r] * al[i] + sum;
            }
        }
#pragma unroll
        for (int i = 0; i < 4; i++) {
#pragma unroll
            for (int j = 0; j < 4; j++) {
                o[i][j] *= al[i];
                Ps[(4 * ty + i) * 65 + 4 * tx + j] = cS[i][j];
            }
        }
        __syncthreads();

        // O += P @ V
        for (int k = 0; k < 64; k++) {
            float a0 = Ps[(4 * ty + 0) * 65 + k];
            float a1 = Ps[(4 * ty + 1) * 65 + k];
            float a2 = Ps[(4 * ty + 2) * 65 + k];
            float a3 = Ps[(4 * ty + 3) * 65 + k];
            float4 bv = *reinterpret_cast<const float4*>(&Vs[k * 64 + 4 * tx]);
            float bb[4] = {bv.x, bv.y, bv.z, bv.w};
#pragma unroll
            for (int j = 0; j < 4; j++) {
                o[0][j] += a0 * bb[j];
                o[1][j] += a1 * bb[j];
                o[2][j] += a2 * bb[j];
                o[3][j] += a3 * bb[j];
            }
        }
        __syncthreads();
    }

    // write out: y[b*T + q][h*64 + d] = o / l
#pragma unroll
    for (int i = 0; i < 4; i++) {
        int r = 4 * ty + i;
        float linv = 1.f / lrow[r];
        size_t row = (size_t)(b * T_ + qt * 64 + r) * C_ + h * 64 + 4 * tx;
        float4 v;
        v.x = o[i][0] * linv; v.y = o[i][1] * linv;
        v.z = o[i][2] * linv; v.w = o[i][3] * linv;
        *reinterpret_cast<float4*>(&y[row]) = v;
    }
}

// ---------------- host launcher ----------------
extern "C" void kernel_launch(void* const* d_in, const int* in_sizes, int n_in,
                              void* d_out, int out_size) {
    const int*   idxw    = (const int*)  d_in[0];
    const float* tok_emb = (const float*)d_in[1];
    const float* pos_emb = (const float*)d_in[2];
    const float* ln1_s   = (const float*)d_in[3];
    const float* ln1_b   = (const float*)d_in[4];
    const float* Wqkv    = (const float*)d_in[5];
    const float* bqkv    = (const float*)d_in[6];
    const float* Wo      = (const float*)d_in[7];
    const float* bo      = (const float*)d_in[8];
    const float* ln2_s   = (const float*)d_in[9];
    const float* ln2_b   = (const float*)d_in[10];
    const float* Wfc     = (const float*)d_in[11];
    const float* bfc     = (const float*)d_in[12];
    const float* Wpr     = (const float*)d_in[13];
    const float* bpr     = (const float*)d_in[14];
    const float* lnf_s   = (const float*)d_in[15];
    const float* lnf_b   = (const float*)d_in[16];
    const float* Whead   = (const float*)d_in[17];
    float* out = (float*)d_out;

    float *x, *h, *qkv, *y, *ff;
    cudaGetSymbolAddress((void**)&x,   g_x);
    cudaGetSymbolAddress((void**)&h,   g_h);
    cudaGetSymbolAddress((void**)&qkv, g_qkv);
    cudaGetSymbolAddress((void**)&y,   g_y);
    cudaGetSymbolAddress((void**)&ff,  g_ff);

    cudaFuncSetAttribute(attn_flash_kernel,
                         cudaFuncAttributeMaxDynamicSharedMemorySize, ATT_SMEM);

    detect_idx_kernel<<<1, 256>>>(idxw);
    embed_kernel<<<(BT_ * C_ + 255) / 256, 256>>>(idxw, tok_emb, pos_emb, x);

    dim3 gQKV((C3_ + TBN - 1) / TBN, BT_ / TBM);
    dim3 gPROJ((C_ + TBN - 1) / TBN, BT_ / TBM);
    dim3 gFC((FF_ + TBN - 1) / TBN, BT_ / TBM);
    dim3 gHEAD((V_ + TBN - 1) / TBN, BT_ / TBM);
    dim3 gATT(T_ / 64, H_, B_);

    for (int l = 0; l < L_; l++) {
        ln_kernel<<<BT_, 256>>>(x, h, ln1_s + (size_t)l * C_, ln1_b + (size_t)l * C_);
        tgemm_kernel<<<gQKV, 256>>>(h, Wqkv + (size_t)l * C_ * C3_,
                                    bqkv + (size_t)l * C3_, nullptr, qkv,
                                    BT_, C3_, C_, 0);
        attn_flash_kernel<<<gATT, 256, ATT_SMEM>>>(qkv, y);
        tgemm_kernel<<<gPROJ, 256>>>(y, Wo + (size_t)l * C_ * C_,
                                     bo + (size_t)l * C_, x, x,
                                     BT_, C_, C_, 0);
        ln_kernel<<<BT_, 256>>>(x, h, ln2_s + (size_t)l * C_, ln2_b + (size_t)l * C_);
        tgemm_kernel<<<gFC, 256>>>(h, Wfc + (size_t)l * C_ * FF_,
                                   bfc + (size_t)l * FF_, nullptr, ff,
                                   BT_, FF_, C_, 1);
        tgemm_kernel<<<gPROJ, 256>>>(ff, Wpr + (size_t)l * FF_ * C_,
                                     bpr + (size_t)l * C_, x, x,
                                     BT_, C_, FF_, 0);
    }

    ln_kernel<<<BT_, 256>>>(x, h, lnf_s, lnf_b);
    tgemm_kernel<<<gHEAD, 256>>>(h, Whead, nullptr, nullptr, out,
                                 BT_, V_, C_, 0);
}

// round 4
// speedup vs baseline: 5.9982x; 1.2592x over previous
#include <cuda_runtime.h>
#include <math.h>
#include <stdint.h>

// ---------------- problem constants ----------------
#define B_   2
#define T_   1024
#define C_   768
#define H_   12
#define D_   64
#define L_   12
#define FF_  3072
#define V_   50257
#define BT_  (B_ * T_)      // 2048
#define C3_  (3 * C_)       // 2304

// ---------------- device scratch ----------------
__device__ float g_x  [BT_ * C_];
__device__ float g_h  [BT_ * C_];
__device__ float g_qkv[BT_ * C3_];
__device__ float g_y  [BT_ * C_];
__device__ float g_ff [BT_ * FF_];
__device__ int   g_idx_is64;

// ---------------- idx dtype detection ----------------
__global__ void detect_idx_kernel(const int* w) {
    __shared__ int found;
    if (threadIdx.x == 0) found = 0;
    __syncthreads();
    for (int i = threadIdx.x; i < BT_ / 2; i += blockDim.x)
        if (w[2 * i + 1] != 0) found = 1;
    __syncthreads();
    if (threadIdx.x == 0) g_idx_is64 = found ? 0 : 1;
}

// ---------------- embedding ----------------
__global__ void embed_kernel(const int* idxw, const float* tok, const float* pos,
                             float* x) {
    int i = blockIdx.x * blockDim.x + threadIdx.x;
    if (i >= BT_ * C_) return;
    int bt = i / C_;
    int c  = i - bt * C_;
    int t  = bt % T_;
    int token = g_idx_is64 ? idxw[2 * bt] : idxw[bt];
    x[i] = tok[(size_t)token * C_ + c] + pos[t * C_ + c];
}

// ---------------- layernorm ----------------
__global__ __launch_bounds__(256)
void ln_kernel(const float* __restrict__ x, float* __restrict__ out,
               const float* __restrict__ s, const float* __restrict__ b) {
    int row = blockIdx.x;
    int tid = threadIdx.x;
    const float* xr = x + (size_t)row * C_;
    float sum = 0.f, sq = 0.f;
    for (int c = tid; c < C_; c += 256) {
        float v = xr[c];
        sum += v; sq += v * v;
    }
    __shared__ float r1[256], r2[256];
    r1[tid] = sum; r2[tid] = sq;
    __syncthreads();
    for (int off = 128; off > 0; off >>= 1) {
        if (tid < off) { r1[tid] += r1[tid + off]; r2[tid] += r2[tid + off]; }
        __syncthreads();
    }
    float mu  = r1[0] * (1.f / C_);
    float var = r2[0] * (1.f / C_) - mu * mu;
    float inv = rsqrtf(var + 1e-5f);
    for (int c = tid; c < C_; c += 256)
        out[(size_t)row * C_ + c] = (xr[c] - mu) * inv * s[c] + b[c];
}

// ---------------- cp.async helpers ----------------
__device__ __forceinline__ uint32_t smem_u32(const void* p) {
    return (uint32_t)__cvta_generic_to_shared(p);
}
__device__ __forceinline__ void cp16(uint32_t dst, const void* src) {
    asm volatile("cp.async.ca.shared.global [%0], [%1], 16;" :: "r"(dst), "l"(src));
}
__device__ __forceinline__ void cp4z(uint32_t dst, const void* src, int srcbytes) {
    asm volatile("cp.async.ca.shared.global [%0], [%1], 4, %2;"
                 :: "r"(dst), "l"(src), "r"(srcbytes));
}
__device__ __forceinline__ void cp_commit() {
    asm volatile("cp.async.commit_group;");
}
template <int Ngrp>
__device__ __forceinline__ void cp_wait() {
    asm volatile("cp.async.wait_group %0;" :: "n"(Ngrp));
}

// ---------------- tf32 helpers ----------------
__device__ __forceinline__ uint32_t tf32_of(float x) {
    uint32_t u;
    asm("cvt.rna.tf32.f32 %0, %1;" : "=r"(u) : "f"(x));
    return u;
}
__device__ __forceinline__ void mma_tf32(float* c, const uint32_t* a, const uint32_t* b) {
    asm volatile(
        "mma.sync.aligned.m16n8k8.row.col.f32.tf32.tf32.f32 "
        "{%0,%1,%2,%3}, {%4,%5,%6,%7}, {%8,%9}, {%0,%1,%2,%3};"
        : "+f"(c[0]), "+f"(c[1]), "+f"(c[2]), "+f"(c[3])
        : "r"(a[0]), "r"(a[1]), "r"(a[2]), "r"(a[3]), "r"(b[0]), "r"(b[1]));
}

// ---------------- tf32 tensor-core GEMM v2: 128x128, cp.async 2-stage ----------------
// 256 threads = 8 warps in 2(m) x 4(n); warp tile 64x32; per warp 4x4 m16n8k8 per k8.
#define GBM 128
#define GBN 128
#define GBK 16
#define ALD 20    // A smem row stride (floats): g*20+tig hits all 32 banks
#define BLD 136   // B smem row stride: tig*8+g hits all 32 banks

__global__ __launch_bounds__(256)
void tgemm_kernel(const float* __restrict__ A, const float* __restrict__ W,
                  const float* __restrict__ bias, const float* __restrict__ Res,
                  float* __restrict__ Cout, int M, int N, int K, int act) {
    __shared__ float sA[2][GBM * ALD];
    __shared__ float sB[2][GBK * BLD];

    int bn = blockIdx.x * GBN;
    int bm = blockIdx.y * GBM;
    int tid  = threadIdx.x;
    int lane = tid & 31;
    int warp = tid >> 5;
    int wm = warp >> 2;            // 0..1
    int wn = warp & 3;             // 0..3
    int g   = lane >> 2;           // 0..7
    int tig = lane & 3;            // 0..3

    // loader mappings
    int a_r  = tid >> 2;           // 0..63 (two iters: +64)
    int a_f4 = (tid & 3) * 4;
    int b_r  = tid >> 5;           // 0..7 (two iters: +8)
    int b_c4 = (tid & 31) * 4;
    bool fullN = ((N & 3) == 0) && (bn + GBN <= N);

    auto load_tiles = [&](int s, int k0) {
#pragma unroll
        for (int it = 0; it < 2; it++) {
            int row = a_r + it * 64;
            cp16(smem_u32(&sA[s][row * ALD + a_f4]),
                 &A[(size_t)(bm + row) * K + k0 + a_f4]);
        }
#pragma unroll
        for (int it = 0; it < 2; it++) {
            int kr = b_r + it * 8;
            if (fullN) {
                cp16(smem_u32(&sB[s][kr * BLD + b_c4]),
                     &W[(size_t)(k0 + kr) * N + bn + b_c4]);
            } else {
#pragma unroll
                for (int j = 0; j < 4; j++) {
                    int col = bn + b_c4 + j;
                    int cc  = col < N ? col : N - 1;
                    cp4z(smem_u32(&sB[s][kr * BLD + b_c4 + j]),
                         &W[(size_t)(k0 + kr) * N + cc], col < N ? 4 : 0);
                }
            }
        }
    };

    float acc[4][4][4];
#pragma unroll
    for (int mi = 0; mi < 4; mi++)
#pragma unroll
        for (int ni = 0; ni < 4; ni++)
#pragma unroll
            for (int e = 0; e < 4; e++) acc[mi][ni][e] = 0.f;

    int KT = K / GBK;
    load_tiles(0, 0);
    cp_commit();

    for (int kt = 0; kt < KT; kt++) {
        if (kt + 1 < KT) {
            load_tiles((kt + 1) & 1, (kt + 1) * GBK);
            cp_commit();
            cp_wait<1>();
        } else {
            cp_wait<0>();
        }
        __syncthreads();

        const float* As = sA[kt & 1];
        const float* Bs = sB[kt & 1];
#pragma unroll
        for (int ks = 0; ks < 2; ks++) {
            int kb = ks * 8;
            uint32_t af[4][4], bf[4][2];
#pragma unroll
            for (int mi = 0; mi < 4; mi++) {
                int m0 = wm * 64 + mi * 16;
                af[mi][0] = tf32_of(As[(m0 + g    ) * ALD + kb + tig    ]);
                af[mi][1] = tf32_of(As[(m0 + g + 8) * ALD + kb + tig    ]);
                af[mi][2] = tf32_of(As[(m0 + g    ) * ALD + kb + tig + 4]);
                af[mi][3] = tf32_of(As[(m0 + g + 8) * ALD + kb + tig + 4]);
            }
#pragma unroll
            for (int ni = 0; ni < 4; ni++) {
                int n0 = wn * 32 + ni * 8;
                bf[ni][0] = tf32_of(Bs[(kb + tig    ) * BLD + n0 + g]);
                bf[ni][1] = tf32_of(Bs[(kb + tig + 4) * BLD + n0 + g]);
            }
#pragma unroll
            for (int mi = 0; mi < 4; mi++)
#pragma unroll
                for (int ni = 0; ni < 4; ni++)
                    mma_tf32(acc[mi][ni], af[mi], bf[ni]);
        }
        __syncthreads();
    }

    // epilogue
#pragma unroll
    for (int mi = 0; mi < 4; mi++) {
        int r0 = bm + wm * 64 + mi * 16 + g;
#pragma unroll
        for (int ni = 0; ni < 4; ni++) {
            int col0 = bn + wn * 32 + ni * 8 + 2 * tig;
#pragma unroll
            for (int e = 0; e < 4; e++) {
                int row = r0 + (e >> 1) * 8;
                int col = col0 + (e & 1);
                if (col < N) {
                    float v = acc[mi][ni][e];
                    if (bias) v += bias[col];
                    if (act == 1)
                        v = 0.5f * v * (1.f + erff(v * 0.70710678118654752f));
                    size_t o = (size_t)row * N + col;
                    if (Res) v += Res[o];
                    Cout[o] = v;
                }
            }
        }
    }
}

// ---------------- flash attention: one CTA per (b, h, 64-q tile) ----------------
#define ATT_SMEM ((3 * 64 * 64 + 64 * 65 + 128) * 4)

__global__ __launch_bounds__(256)
void attn_flash_kernel(const float* __restrict__ qkv, float* __restrict__ y) {
    extern __shared__ float sm[];
    float* Qs   = sm;
    float* Ks   = Qs + 64 * 64;
    float* Vs   = Ks + 64 * 64;
    float* Ps   = Vs + 64 * 64;
    float* mrow = Ps + 64 * 65;
    float* lrow = mrow + 64;

    int qt  = blockIdx.x;
    int h   = blockIdx.y;
    int b   = blockIdx.z;
    int tid = threadIdx.x;
    int tx  = tid & 15;
    int ty  = tid >> 4;
    const float scale = 0.125f;
    const float* base = qkv + (size_t)b * T_ * C3_;

    {
        int r  = tid >> 2;
        int d0 = (tid & 3) * 16;
        const float* qp = base + (size_t)(qt * 64 + r) * C3_ + h * 64 + d0;
#pragma unroll
        for (int i = 0; i < 4; i++) {
            float4 v = *reinterpret_cast<const float4*>(&qp[4 * i]);
            Qs[(d0 + 4 * i + 0) * 64 + r] = v.x;
            Qs[(d0 + 4 * i + 1) * 64 + r] = v.y;
            Qs[(d0 + 4 * i + 2) * 64 + r] = v.z;
            Qs[(d0 + 4 * i + 3) * 64 + r] = v.w;
        }
    }
    if (tid < 64) { mrow[tid] = -1e30f; lrow[tid] = 0.f; }

    float o[4][4];
#pragma unroll
    for (int i = 0; i < 4; i++)
#pragma unroll
        for (int j = 0; j < 4; j++) o[i][j] = 0.f;
    __syncthreads();

    for (int kt = 0; kt <= qt; kt++) {
        {
            int r  = tid >> 2;
            int d0 = (tid & 3) * 16;
            const float* kp = base + (size_t)(kt * 64 + r) * C3_ + C_ + h * 64 + d0;
            const float* vp = kp + C_;
#pragma unroll
            for (int i = 0; i < 4; i++) {
                float4 v = *reinterpret_cast<const float4*>(&kp[4 * i]);
                Ks[(d0 + 4 * i + 0) * 64 + r] = v.x;
                Ks[(d0 + 4 * i + 1) * 64 + r] = v.y;
                Ks[(d0 + 4 * i + 2) * 64 + r] = v.z;
                Ks[(d0 + 4 * i + 3) * 64 + r] = v.w;
            }
#pragma unroll
            for (int i = 0; i < 4; i++) {
                float4 v = *reinterpret_cast<const float4*>(&vp[4 * i]);
                *reinterpret_cast<float4*>(&Vs[r * 64 + d0 + 4 * i]) = v;
            }
        }
        __syncthreads();

        float cS[4][4];
#pragma unroll
        for (int i = 0; i < 4; i++)
#pragma unroll
            for (int j = 0; j < 4; j++) cS[i][j] = 0.f;
        for (int d = 0; d < 64; d++) {
            float4 aq = *reinterpret_cast<const float4*>(&Qs[d * 64 + 4 * ty]);
            float4 bk = *reinterpret_cast<const float4*>(&Ks[d * 64 + 4 * tx]);
            float a[4] = {aq.x, aq.y, aq.z, aq.w};
            float bb[4] = {bk.x, bk.y, bk.z, bk.w};
#pragma unroll
            for (int i = 0; i < 4; i++)
#pragma unroll
                for (int j = 0; j < 4; j++) cS[i][j] += a[i] * bb[j];
        }

        float al[4];
        bool diag = (kt == qt);
#pragma unroll
        for (int i = 0; i < 4; i++) {
            int r  = 4 * ty + i;
            int qg = qt * 64 + r;
            float rmax = -1e30f;
#pragma unroll
            for (int j = 0; j < 4; j++) {
                float s = cS[i][j] * scale;
                if (diag && (kt * 64 + 4 * tx + j) > qg) s = -1e30f;
                cS[i][j] = s;
                rmax = fmaxf(rmax, s);
            }
#pragma unroll
            for (int off = 8; off > 0; off >>= 1)
                rmax = fmaxf(rmax, __shfl_xor_sync(0xffffffffu, rmax, off));
            float mo = mrow[r];
            float mn = fmaxf(mo, rmax);
            float sum = 0.f;
#pragma unroll
            for (int j = 0; j < 4; j++) {
                float p = __expf(cS[i][j] - mn);
                cS[i][j] = p;
                sum += p;
            }
#pragma unroll
            for (int off = 8; off > 0; off >>= 1)
                sum += __shfl_xor_sync(0xffffffffu, sum, off);
            al[i] = __expf(mo - mn);
            if (tx == 0) {
                mrow[r] = mn;
                lrow[r] = lrow[r] * al[i] + sum;
            }
        }
#pragma unroll
        for (int i = 0; i < 4; i++) {
#pragma unroll
            for (int j = 0; j < 4; j++) {
                o[i][j] *= al[i];
                Ps[(4 * ty + i) * 65 + 4 * tx + j] = cS[i][j];
            }
        }
        __syncthreads();

        for (int k = 0; k < 64; k++) {
            float a0 = Ps[(4 * ty + 0) * 65 + k];
            float a1 = Ps[(4 * ty + 1) * 65 + k];
            float a2 = Ps[(4 * ty + 2) * 65 + k];
            float a3 = Ps[(4 * ty + 3) * 65 + k];
            float4 bv = *reinterpret_cast<const float4*>(&Vs[k * 64 + 4 * tx]);
            float bb[4] = {bv.x, bv.y, bv.z, bv.w};
#pragma unroll
            for (int j = 0; j < 4; j++) {
                o[0][j] += a0 * bb[j];
                o[1][j] += a1 * bb[j];
                o[2][j] += a2 * bb[j];
                o[3][j] += a3 * bb[j];
            }
        }
        __syncthreads();
    }

#pragma unroll
    for (int i = 0; i < 4; i++) {
        int r = 4 * ty + i;
        float linv = 1.f / lrow[r];
        size_t row = (size_t)(b * T_ + qt * 64 + r) * C_ + h * 64 + 4 * tx;
        float4 v;
        v.x = o[i][0] * linv; v.y = o[i][1] * linv;
        v.z = o[i][2] * linv; v.w = o[i][3] * linv;
        *reinterpret_cast<float4*>(&y[row]) = v;
    }
}

// ---------------- host launcher ----------------
extern "C" void kernel_launch(void* const* d_in, const int* in_sizes, int n_in,
                              void* d_out, int out_size) {
    const int*   idxw    = (const int*)  d_in[0];
    const float* tok_emb = (const float*)d_in[1];
    const float* pos_emb = (const float*)d_in[2];
    const float* ln1_s   = (const float*)d_in[3];
    const float* ln1_b   = (const float*)d_in[4];
    const float* Wqkv    = (const float*)d_in[5];
    const float* bqkv    = (const float*)d_in[6];
    const float* Wo      = (const float*)d_in[7];
    const float* bo      = (const float*)d_in[8];
    const float* ln2_s   = (const float*)d_in[9];
    const float* ln2_b   = (const float*)d_in[10];
    const float* Wfc     = (const float*)d_in[11];
    const float* bfc     = (const float*)d_in[12];
    const float* Wpr     = (const float*)d_in[13];
    const float* bpr     = (const float*)d_in[14];
    const float* lnf_s   = (const float*)d_in[15];
    const float* lnf_b   = (const float*)d_in[16];
    const float* Whead   = (const float*)d_in[17];
    float* out = (float*)d_out;

    float *x, *h, *qkv, *y, *ff;
    cudaGetSymbolAddress((void**)&x,   g_x);
    cudaGetSymbolAddress((void**)&h,   g_h);
    cudaGetSymbolAddress((void**)&qkv, g_qkv);
    cudaGetSymbolAddress((void**)&y,   g_y);
    cudaGetSymbolAddress((void**)&ff,  g_ff);

    cudaFuncSetAttribute(attn_flash_kernel,
                         cudaFuncAttributeMaxDynamicSharedMemorySize, ATT_SMEM);

    detect_idx_kernel<<<1, 256>>>(idxw);
    embed_kernel<<<(BT_ * C_ + 255) / 256, 256>>>(idxw, tok_emb, pos_emb, x);

    dim3 gQKV(C3_ / GBN, BT_ / GBM);
    dim3 gPROJ(C_ / GBN, BT_ / GBM);
    dim3 gFC(FF_ / GBN, BT_ / GBM);
    dim3 gHEAD((V_ + GBN - 1) / GBN, BT_ / GBM);
    dim3 gATT(T_ / 64, H_, B_);

    for (int l = 0; l < L_; l++) {
        ln_kernel<<<BT_, 256>>>(x, h, ln1_s + (size_t)l * C_, ln1_b + (size_t)l * C_);
        tgemm_kernel<<<gQKV, 256>>>(h, Wqkv + (size_t)l * C_ * C3_,
                                    bqkv + (size_t)l * C3_, nullptr, qkv,
                                    BT_, C3_, C_, 0);
        attn_flash_kernel<<<gATT, 256, ATT_SMEM>>>(qkv, y);
        tgemm_kernel<<<gPROJ, 256>>>(y, Wo + (size_t)l * C_ * C_,
                                     bo + (size_t)l * C_, x, x,
                                     BT_, C_, C_, 0);
        ln_kernel<<<BT_, 256>>>(x, h, ln2_s + (size_t)l * C_, ln2_b + (size_t)l * C_);
        tgemm_kernel<<<gFC, 256>>>(h, Wfc + (size_t)l * C_ * FF_,
                                   bfc + (size_t)l * FF_, nullptr, ff,
                                   BT_, FF_, C_, 1);
        tgemm_kernel<<<gPROJ, 256>>>(ff, Wpr + (size_t)l * FF_ * C_,
                                     bpr + (size_t)l * C_, x, x,
                                     BT_, C_, FF_, 0);
    }

    ln_kernel<<<BT_, 256>>>(x, h, lnf_s, lnf_b);
    tgemm_kernel<<<gHEAD, 256>>>(h, Whead, nullptr, nullptr, out,
                                 BT_, V_, C_, 0);
}

// round 5
// speedup vs baseline: 7.1940x; 1.1994x over previous
#include <cuda_runtime.h>
#include <math.h>
#include <stdint.h>

// ---------------- problem constants ----------------
#define B_   2
#define T_   1024
#define C_   768
#define H_   12
#define D_   64
#define L_   12
#define FF_  3072
#define V_   50257
#define VP_  50304          // 393 * 128, padded head vocab
#define BT_  (B_ * T_)      // 2048
#define C3_  (3 * C_)       // 2304

// ---------------- device scratch ----------------
__device__ float g_x  [BT_ * C_];
__device__ float g_h  [BT_ * C_];
__device__ float g_qkv[BT_ * C3_];
__device__ float g_y  [BT_ * C_];
__device__ float g_ff [BT_ * FF_];
__device__ float g_Wp [C_ * VP_];   // padded Whead
__device__ int   g_idx_is64;

// ---------------- idx dtype detection ----------------
__global__ void detect_idx_kernel(const int* w) {
    __shared__ int found;
    if (threadIdx.x == 0) found = 0;
    __syncthreads();
    for (int i = threadIdx.x; i < BT_ / 2; i += blockDim.x)
        if (w[2 * i + 1] != 0) found = 1;
    __syncthreads();
    if (threadIdx.x == 0) g_idx_is64 = found ? 0 : 1;
}

// ---------------- embedding ----------------
__global__ void embed_kernel(const int* idxw, const float* tok, const float* pos,
                             float* x) {
    int i = blockIdx.x * blockDim.x + threadIdx.x;
    if (i >= BT_ * C_) return;
    int bt = i / C_;
    int c  = i - bt * C_;
    int t  = bt % T_;
    int token = g_idx_is64 ? idxw[2 * bt] : idxw[bt];
    x[i] = tok[(size_t)token * C_ + c] + pos[t * C_ + c];
}

// ---------------- pad Whead to stride VP_ ----------------
__global__ void padW_kernel(const float* __restrict__ W, float* __restrict__ Wp) {
    int i = blockIdx.x * blockDim.x + threadIdx.x;
    if (i >= C_ * VP_) return;
    int row = i / VP_;
    int col = i - row * VP_;
    Wp[i] = (col < V_) ? W[(size_t)row * V_ + col] : 0.f;
}

// ---------------- layernorm ----------------
__global__ __launch_bounds__(256)
void ln_kernel(const float* __restrict__ x, float* __restrict__ out,
               const float* __restrict__ s, const float* __restrict__ b) {
    int row = blockIdx.x;
    int tid = threadIdx.x;
    const float* xr = x + (size_t)row * C_;
    float sum = 0.f, sq = 0.f;
    for (int c = tid; c < C_; c += 256) {
        float v = xr[c];
        sum += v; sq += v * v;
    }
    __shared__ float r1[256], r2[256];
    r1[tid] = sum; r2[tid] = sq;
    __syncthreads();
    for (int off = 128; off > 0; off >>= 1) {
        if (tid < off) { r1[tid] += r1[tid + off]; r2[tid] += r2[tid + off]; }
        __syncthreads();
    }
    float mu  = r1[0] * (1.f / C_);
    float var = r2[0] * (1.f / C_) - mu * mu;
    float inv = rsqrtf(var + 1e-5f);
    for (int c = tid; c < C_; c += 256)
        out[(size_t)row * C_ + c] = (xr[c] - mu) * inv * s[c] + b[c];
}

// ---------------- cp.async helpers ----------------
__device__ __forceinline__ uint32_t smem_u32(const void* p) {
    return (uint32_t)__cvta_generic_to_shared(p);
}
__device__ __forceinline__ void cp16(uint32_t dst, const void* src) {
    asm volatile("cp.async.ca.shared.global [%0], [%1], 16;" :: "r"(dst), "l"(src));
}
__device__ __forceinline__ void cp_commit() {
    asm volatile("cp.async.commit_group;");
}
template <int Ngrp>
__device__ __forceinline__ void cp_wait() {
    asm volatile("cp.async.wait_group %0;" :: "n"(Ngrp));
}

// ---------------- tf32 helpers ----------------
__device__ __forceinline__ uint32_t tf32_of(float x) {
    uint32_t u;
    asm("cvt.rna.tf32.f32 %0, %1;" : "=r"(u) : "f"(x));
    return u;
}
__device__ __forceinline__ void mma_tf32(float* c, const uint32_t* a, const uint32_t* b) {
    asm volatile(
        "mma.sync.aligned.m16n8k8.row.col.f32.tf32.tf32.f32 "
        "{%0,%1,%2,%3}, {%4,%5,%6,%7}, {%8,%9}, {%0,%1,%2,%3};"
        : "+f"(c[0]), "+f"(c[1]), "+f"(c[2]), "+f"(c[3])
        : "r"(a[0]), "r"(a[1]), "r"(a[2]), "r"(a[3]), "r"(b[0]), "r"(b[1]));
}

// ---------------- tf32 GEMM v3: 128x128, 3-stage cp.async, 1 sync/iter ----------------
// 256 threads = 8 warps (2m x 4n); warp tile 64x32.
// A: [row][k] stride ALD; B: [k][col] stride BLD. ldw = W row stride, Nout = logical N.
#define GBM 128
#define GBN 128
#define GBK 16
#define ALD 20
#define BLD 136
#define A_ST (GBM * ALD)          // 2560 floats / stage
#define B_ST (GBK * BLD)          // 2176 floats / stage
#define GEMM_SMEM (3 * (A_ST + B_ST) * 4)

__global__ __launch_bounds__(256)
void tgemm_kernel(const float* __restrict__ A, const float* __restrict__ W,
                  const float* __restrict__ bias, const float* __restrict__ Res,
                  float* __restrict__ Cout, int M, int Nout, int K, int ldw, int act) {
    extern __shared__ float smg[];
    float* sA = smg;                    // 3 stages
    float* sB = smg + 3 * A_ST;

    int bn = blockIdx.x * GBN;
    int bm = blockIdx.y * GBM;
    int tid  = threadIdx.x;
    int lane = tid & 31;
    int warp = tid >> 5;
    int wm = warp >> 2;
    int wn = warp & 3;
    int g   = lane >> 2;
    int tig = lane & 3;

    int a_r  = tid >> 2;
    int a_f4 = (tid & 3) * 4;
    int b_r  = tid >> 5;
    int b_c4 = (tid & 31) * 4;

    auto load_tiles = [&](int s, int k0) {
        float* As = sA + s * A_ST;
        float* Bs = sB + s * B_ST;
#pragma unroll
        for (int it = 0; it < 2; it++) {
            int row = a_r + it * 64;
            cp16(smem_u32(&As[row * ALD + a_f4]),
                 &A[(size_t)(bm + row) * K + k0 + a_f4]);
        }
#pragma unroll
        for (int it = 0; it < 2; it++) {
            int kr = b_r + it * 8;
            cp16(smem_u32(&Bs[kr * BLD + b_c4]),
                 &W[(size_t)(k0 + kr) * ldw + bn + b_c4]);
        }
    };

    float acc[4][4][4];
#pragma unroll
    for (int mi = 0; mi < 4; mi++)
#pragma unroll
        for (int ni = 0; ni < 4; ni++)
#pragma unroll
            for (int e = 0; e < 4; e++) acc[mi][ni][e] = 0.f;

    int KT = K / GBK;
    load_tiles(0, 0);
    cp_commit();
    if (KT > 1) { load_tiles(1, GBK); cp_commit(); }

    for (int kt = 0; kt < KT; kt++) {
        if (kt + 1 < KT) cp_wait<1>(); else cp_wait<0>();
        __syncthreads();
        if (kt + 2 < KT) { load_tiles((kt + 2) % 3, (kt + 2) * GBK); cp_commit(); }

        const float* As = sA + (kt % 3) * A_ST;
        const float* Bs = sB + (kt % 3) * B_ST;
#pragma unroll
        for (int ks = 0; ks < 2; ks++) {
            int kb = ks * 8;
            uint32_t af[4][4], bf[4][2];
#pragma unroll
            for (int mi = 0; mi < 4; mi++) {
                int m0 = wm * 64 + mi * 16;
                af[mi][0] = tf32_of(As[(m0 + g    ) * ALD + kb + tig    ]);
                af[mi][1] = tf32_of(As[(m0 + g + 8) * ALD + kb + tig    ]);
                af[mi][2] = tf32_of(As[(m0 + g    ) * ALD + kb + tig + 4]);
                af[mi][3] = tf32_of(As[(m0 + g + 8) * ALD + kb + tig + 4]);
            }
#pragma unroll
            for (int ni = 0; ni < 4; ni++) {
                int n0 = wn * 32 + ni * 8;
                bf[ni][0] = tf32_of(Bs[(kb + tig    ) * BLD + n0 + g]);
                bf[ni][1] = tf32_of(Bs[(kb + tig + 4) * BLD + n0 + g]);
            }
#pragma unroll
            for (int mi = 0; mi < 4; mi++)
#pragma unroll
                for (int ni = 0; ni < 4; ni++)
                    mma_tf32(acc[mi][ni], af[mi], bf[ni]);
        }
    }
    __syncthreads();

    // epilogue: pairs (e, e+1) share a row, adjacent cols
    bool evenN = ((Nout & 1) == 0);
#pragma unroll
    for (int mi = 0; mi < 4; mi++) {
        int r0 = bm + wm * 64 + mi * 16 + g;
#pragma unroll
        for (int ni = 0; ni < 4; ni++) {
            int col0 = bn + wn * 32 + ni * 8 + 2 * tig;
#pragma unroll
            for (int ep = 0; ep < 4; ep += 2) {
                int row = r0 + (ep >> 1) * 8;
                float v0 = acc[mi][ni][ep];
                float v1 = acc[mi][ni][ep + 1];
                if (bias) { v0 += bias[col0]; v1 += bias[col0 + 1]; }
                if (act == 1) {
                    v0 = 0.5f * v0 * (1.f + erff(v0 * 0.70710678118654752f));
                    v1 = 0.5f * v1 * (1.f + erff(v1 * 0.70710678118654752f));
                }
                size_t o = (size_t)row * Nout + col0;
                if (evenN) {
                    if (Res) { v0 += Res[o]; v1 += Res[o + 1]; }
                    float2 st = {v0, v1};
                    *reinterpret_cast<float2*>(&Cout[o]) = st;
                } else {
                    if (col0 < Nout) {
                        if (Res) v0 += Res[o];
                        Cout[o] = v0;
                    }
                    if (col0 + 1 < Nout) {
                        if (Res) v1 += Res[o + 1];
                        Cout[o + 1] = v1;
                    }
                }
            }
        }
    }
}

// ---------------- flash attention: one CTA per (b, h, 64-q tile) ----------------
#define ATT_SMEM ((3 * 64 * 64 + 64 * 65 + 128) * 4)

__global__ __launch_bounds__(256)
void attn_flash_kernel(const float* __restrict__ qkv, float* __restrict__ y) {
    extern __shared__ float sm[];
    float* Qs   = sm;
    float* Ks   = Qs + 64 * 64;
    float* Vs   = Ks + 64 * 64;
    float* Ps   = Vs + 64 * 64;
    float* mrow = Ps + 64 * 65;
    float* lrow = mrow + 64;

    int qt  = blockIdx.x;
    int h   = blockIdx.y;
    int b   = blockIdx.z;
    int tid = threadIdx.x;
    int tx  = tid & 15;
    int ty  = tid >> 4;
    const float scale = 0.125f;
    const float* base = qkv + (size_t)b * T_ * C3_;

    {
        int r  = tid >> 2;
        int d0 = (tid & 3) * 16;
        const float* qp = base + (size_t)(qt * 64 + r) * C3_ + h * 64 + d0;
#pragma unroll
        for (int i = 0; i < 4; i++) {
            float4 v = *reinterpret_cast<const float4*>(&qp[4 * i]);
            Qs[(d0 + 4 * i + 0) * 64 + r] = v.x;
            Qs[(d0 + 4 * i + 1) * 64 + r] = v.y;
            Qs[(d0 + 4 * i + 2) * 64 + r] = v.z;
            Qs[(d0 + 4 * i + 3) * 64 + r] = v.w;
        }
    }
    if (tid < 64) { mrow[tid] = -1e30f; lrow[tid] = 0.f; }

    float o[4][4];
#pragma unroll
    for (int i = 0; i < 4; i++)
#pragma unroll
        for (int j = 0; j < 4; j++) o[i][j] = 0.f;
    __syncthreads();

    for (int kt = 0; kt <= qt; kt++) {
        {
            int r  = tid >> 2;
            int d0 = (tid & 3) * 16;
            const float* kp = base + (size_t)(kt * 64 + r) * C3_ + C_ + h * 64 + d0;
            const float* vp = kp + C_;
#pragma unroll
            for (int i = 0; i < 4; i++) {
                float4 v = *reinterpret_cast<const float4*>(&kp[4 * i]);
                Ks[(d0 + 4 * i + 0) * 64 + r] = v.x;
                Ks[(d0 + 4 * i + 1) * 64 + r] = v.y;
                Ks[(d0 + 4 * i + 2) * 64 + r] = v.z;
                Ks[(d0 + 4 * i + 3) * 64 + r] = v.w;
            }
#pragma unroll
            for (int i = 0; i < 4; i++) {
                float4 v = *reinterpret_cast<const float4*>(&vp[4 * i]);
                *reinterpret_cast<float4*>(&Vs[r * 64 + d0 + 4 * i]) = v;
            }
        }
        __syncthreads();

        float cS[4][4];
#pragma unroll
        for (int i = 0; i < 4; i++)
#pragma unroll
            for (int j = 0; j < 4; j++) cS[i][j] = 0.f;
        for (int d = 0; d < 64; d++) {
            float4 aq = *reinterpret_cast<const float4*>(&Qs[d * 64 + 4 * ty]);
            float4 bk = *reinterpret_cast<const float4*>(&Ks[d * 64 + 4 * tx]);
            float a[4] = {aq.x, aq.y, aq.z, aq.w};
            float bb[4] = {bk.x, bk.y, bk.z, bk.w};
#pragma unroll
            for (int i = 0; i < 4; i++)
#pragma unroll
                for (int j = 0; j < 4; j++) cS[i][j] += a[i] * bb[j];
        }

        float al[4];
        bool diag = (kt == qt);
#pragma unroll
        for (int i = 0; i < 4; i++) {
            int r  = 4 * ty + i;
            int qg = qt * 64 + r;
            float rmax = -1e30f;
#pragma unroll
            for (int j = 0; j < 4; j++) {
                float s = cS[i][j] * scale;
                if (diag && (kt * 64 + 4 * tx + j) > qg) s = -1e30f;
                cS[i][j] = s;
                rmax = fmaxf(rmax, s);
            }
#pragma unroll
            for (int off = 8; off > 0; off >>= 1)
                rmax = fmaxf(rmax, __shfl_xor_sync(0xffffffffu, rmax, off));
            float mo = mrow[r];
            float mn = fmaxf(mo, rmax);
            float sum = 0.f;
#pragma unroll
            for (int j = 0; j < 4; j++) {
                float p = __expf(cS[i][j] - mn);
                cS[i][j] = p;
                sum += p;
            }
#pragma unroll
            for (int off = 8; off > 0; off >>= 1)
                sum += __shfl_xor_sync(0xffffffffu, sum, off);
            al[i] = __expf(mo - mn);
            if (tx == 0) {
                mrow[r] = mn;
                lrow[r] = lrow[r] * al[i] + sum;
            }
        }
#pragma unroll
        for (int i = 0; i < 4; i++) {
#pragma unroll
            for (int j = 0; j < 4; j++) {
                o[i][j] *= al[i];
                Ps[(4 * ty + i) * 65 + 4 * tx + j] = cS[i][j];
            }
        }
        __syncthreads();

        for (int k = 0; k < 64; k++) {
            float a0 = Ps[(4 * ty + 0) * 65 + k];
            float a1 = Ps[(4 * ty + 1) * 65 + k];
            float a2 = Ps[(4 * ty + 2) * 65 + k];
            float a3 = Ps[(4 * ty + 3) * 65 + k];
            float4 bv = *reinterpret_cast<const float4*>(&Vs[k * 64 + 4 * tx]);
            float bb[4] = {bv.x, bv.y, bv.z, bv.w};
#pragma unroll
            for (int j = 0; j < 4; j++) {
                o[0][j] += a0 * bb[j];
                o[1][j] += a1 * bb[j];
                o[2][j] += a2 * bb[j];
                o[3][j] += a3 * bb[j];
            }
        }
        __syncthreads();
    }

#pragma unroll
    for (int i = 0; i < 4; i++) {
        int r = 4 * ty + i;
        float linv = 1.f / lrow[r];
        size_t row = (size_t)(b * T_ + qt * 64 + r) * C_ + h * 64 + 4 * tx;
        float4 v;
        v.x = o[i][0] * linv; v.y = o[i][1] * linv;
        v.z = o[i][2] * linv; v.w = o[i][3] * linv;
        *reinterpret_cast<float4*>(&y[row]) = v;
    }
}

// ---------------- host launcher ----------------
extern "C" void kernel_launch(void* const* d_in, const int* in_sizes, int n_in,
                              void* d_out, int out_size) {
    const int*   idxw    = (const int*)  d_in[0];
    const float* tok_emb = (const float*)d_in[1];
    const float* pos_emb = (const float*)d_in[2];
    const float* ln1_s   = (const float*)d_in[3];
    const float* ln1_b   = (const float*)d_in[4];
    const float* Wqkv    = (const float*)d_in[5];
    const float* bqkv    = (const float*)d_in[6];
    const float* Wo      = (const float*)d_in[7];
    const float* bo      = (const float*)d_in[8];
    const float* ln2_s   = (const float*)d_in[9];
    const float* ln2_b   = (const float*)d_in[10];
    const float* Wfc     = (const float*)d_in[11];
    const float* bfc     = (const float*)d_in[12];
    const float* Wpr     = (const float*)d_in[13];
    const float* bpr     = (const float*)d_in[14];
    const float* lnf_s   = (const float*)d_in[15];
    const float* lnf_b   = (const float*)d_in[16];
    const float* Whead   = (const float*)d_in[17];
    float* out = (float*)d_out;

    float *x, *h, *qkv, *y, *ff, *Wp;
    cudaGetSymbolAddress((void**)&x,   g_x);
    cudaGetSymbolAddress((void**)&h,   g_h);
    cudaGetSymbolAddress((void**)&qkv, g_qkv);
    cudaGetSymbolAddress((void**)&y,   g_y);
    cudaGetSymbolAddress((void**)&ff,  g_ff);
    cudaGetSymbolAddress((void**)&Wp,  g_Wp);

    cudaFuncSetAttribute(attn_flash_kernel,
                         cudaFuncAttributeMaxDynamicSharedMemorySize, ATT_SMEM);
    cudaFuncSetAttribute(tgemm_kernel,
                         cudaFuncAttributeMaxDynamicSharedMemorySize, GEMM_SMEM);

    detect_idx_kernel<<<1, 256>>>(idxw);
    embed_kernel<<<(BT_ * C_ + 255) / 256, 256>>>(idxw, tok_emb, pos_emb, x);
    padW_kernel<<<(C_ * VP_ + 255) / 256, 256>>>(Whead, Wp);

    dim3 gQKV(C3_ / GBN, BT_ / GBM);
    dim3 gPROJ(C_ / GBN, BT_ / GBM);
    dim3 gFC(FF_ / GBN, BT_ / GBM);
    dim3 gHEAD(VP_ / GBN, BT_ / GBM);
    dim3 gATT(T_ / 64, H_, B_);

    for (int l = 0; l < L_; l++) {
        ln_kernel<<<BT_, 256>>>(x, h, ln1_s + (size_t)l * C_, ln1_b + (size_t)l * C_);
        tgemm_kernel<<<gQKV, 256, GEMM_SMEM>>>(h, Wqkv + (size_t)l * C_ * C3_,
                                    bqkv + (size_t)l * C3_, nullptr, qkv,
                                    BT_, C3_, C_, C3_, 0);
        attn_flash_kernel<<<gATT, 256, ATT_SMEM>>>(qkv, y);
        tgemm_kernel<<<gPROJ, 256, GEMM_SMEM>>>(y, Wo + (size_t)l * C_ * C_,
                                     bo + (size_t)l * C_, x, x,
                                     BT_, C_, C_, C_, 0);
        ln_kernel<<<BT_, 256>>>(x, h, ln2_s + (size_t)l * C_, ln2_b + (size_t)l * C_);
        tgemm_kernel<<<gFC, 256, GEMM_SMEM>>>(h, Wfc + (size_t)l * C_ * FF_,
                                   bfc + (size_t)l * FF_, nullptr, ff,
                                   BT_, FF_, C_, FF_, 1);
        tgemm_kernel<<<gPROJ, 256, GEMM_SMEM>>>(ff, Wpr + (size_t)l * FF_ * C_,
                                     bpr + (size_t)l * C_, x, x,
                                     BT_, C_, FF_, C_, 0);
    }

    ln_kernel<<<BT_, 256>>>(x, h, lnf_s, lnf_b);
    tgemm_kernel<<<gHEAD, 256, GEMM_SMEM>>>(h, Wp, nullptr, nullptr, out,
                                 BT_, V_, C_, VP_, 0);
}